// round 1
// baseline (speedup 1.0000x reference)
#include <cuda_runtime.h>
#include <cuda_bf16.h>
#include <math.h>

#define HIDDEN    128
#define STATE_DIM 6
#define NUM_STEPS 8
#define MAX_STD   2.0f
#define MIN_STD   0.1f

// Transposed weight scratch (allocation-free __device__ globals).
// Layout: Wt[j*HIDDEN + i] = W[i*HIDDEN + j]  (column j of W contiguous over i)
__device__ float g_rec1t[HIDDEN * HIDDEN];
__device__ float g_fc2t [HIDDEN * HIDDEN];
__device__ float g_rec2t[HIDDEN * HIDDEN];
__device__ float g_fc1t [STATE_DIM * HIDDEN];   // fc1t[d*HIDDEN + i] = w_fc1[i*STATE_DIM + d]

__global__ void snn_transpose_kernel(const float* __restrict__ w_fc1,
                                     const float* __restrict__ w_rec1,
                                     const float* __restrict__ w_fc2,
                                     const float* __restrict__ w_rec2) {
    int idx = blockIdx.x * blockDim.x + threadIdx.x;   // 0 .. 16383
    if (idx < HIDDEN * HIDDEN) {
        int i = idx / HIDDEN;
        int j = idx % HIDDEN;
        int t = j * HIDDEN + i;
        g_rec1t[t] = w_rec1[idx];
        g_fc2t [t] = w_fc2 [idx];
        g_rec2t[t] = w_rec2[idx];
        if (idx < HIDDEN * STATE_DIM) {
            int ii = idx / STATE_DIM;
            int d  = idx % STATE_DIM;
            g_fc1t[d * HIDDEN + ii] = w_fc1[idx];
        }
    }
}

// Accumulate sum over set bits j of mask into acc[0..3] for units 4*lane+k.
// Mask layout: word k, bit l  <->  unit 4*l + k.
__device__ __forceinline__ void gather4(const float* __restrict__ Wt,
                                        const unsigned m[4], int lane,
                                        float acc[4]) {
#pragma unroll
    for (int w = 0; w < 4; w++) {
        unsigned mm = m[w];
        while (mm) {
            int l = __ffs(mm) - 1;
            mm &= mm - 1;
            int j = 4 * l + w;
            float4 v = *reinterpret_cast<const float4*>(Wt + j * HIDDEN + 4 * lane);
            acc[0] += v.x; acc[1] += v.y; acc[2] += v.z; acc[3] += v.w;
        }
    }
}

__global__ void __launch_bounds__(256)
snn_main_kernel(const float* __restrict__ state,
                const float* __restrict__ w_mean,
                const float* __restrict__ w_std,
                const float* __restrict__ p_a1, const float* __restrict__ p_b1,
                const float* __restrict__ p_t1, const float* __restrict__ p_a2,
                const float* __restrict__ p_b2, const float* __restrict__ p_t2,
                float* __restrict__ out, int B) {
    int gtid = blockIdx.x * blockDim.x + threadIdx.x;
    int b    = gtid >> 5;          // one warp per batch element
    int lane = threadIdx.x & 31;
    if (b >= B) return;

    const float a1 = fminf(fmaxf(*p_a1, 0.f), 1.f);
    const float b1 = fminf(fmaxf(*p_b1, 0.f), 1.f);
    const float a2 = fminf(fmaxf(*p_a2, 0.f), 1.f);
    const float b2 = fminf(fmaxf(*p_b2, 0.f), 1.f);
    const float thr1 = *p_t1;
    const float thr2 = *p_t2;

    // cur1_in[i] = sum_d state[b,d] * w_fc1[i,d]   (constant across steps)
    float cur1[4] = {0.f, 0.f, 0.f, 0.f};
#pragma unroll
    for (int d = 0; d < STATE_DIM; d++) {
        float sd = __ldg(state + (long)b * STATE_DIM + d);
        float4 w = *reinterpret_cast<const float4*>(g_fc1t + d * HIDDEN + 4 * lane);
        cur1[0] += sd * w.x; cur1[1] += sd * w.y;
        cur1[2] += sd * w.z; cur1[3] += sd * w.w;
    }

    float syn1[4] = {0.f, 0.f, 0.f, 0.f}, mem1[4] = {0.f, 0.f, 0.f, 0.f};
    float syn2[4] = {0.f, 0.f, 0.f, 0.f}, mem2[4] = {0.f, 0.f, 0.f, 0.f};
    float cnt2[4] = {0.f, 0.f, 0.f, 0.f};
    unsigned m1[4] = {0u, 0u, 0u, 0u};   // spk1 bitmask (prev step)
    unsigned m2[4] = {0u, 0u, 0u, 0u};   // spk2 bitmask (prev step)

#pragma unroll
    for (int t = 0; t < NUM_STEPS; t++) {
        // ---- layer 1 ----
        float r1[4] = {0.f, 0.f, 0.f, 0.f};
        gather4(g_rec1t, m1, lane, r1);          // spk1_prev @ w_rec1.T

        unsigned nm1[4];
#pragma unroll
        for (int k = 0; k < 4; k++) {
            syn1[k] = a1 * syn1[k] + cur1[k] + r1[k];
            // reset1 == spk1_prev (both = heaviside(mem1_prev - thr1))
            float rb = ((m1[k] >> lane) & 1u) ? thr1 : 0.f;
            mem1[k] = b1 * mem1[k] + syn1[k] - rb;
            nm1[k] = __ballot_sync(0xffffffffu, (mem1[k] - thr1) > 0.f);
        }

        // ---- layer 2 ----
        float acc2[4] = {0.f, 0.f, 0.f, 0.f};
        gather4(g_fc2t,  nm1, lane, acc2);       // spk1_new  @ w_fc2.T
        gather4(g_rec2t, m2,  lane, acc2);       // spk2_prev @ w_rec2.T

        unsigned nm2[4];
#pragma unroll
        for (int k = 0; k < 4; k++) {
            syn2[k] = a2 * syn2[k] + acc2[k];
            float rb = ((m2[k] >> lane) & 1u) ? thr2 : 0.f;
            mem2[k] = b2 * mem2[k] + syn2[k] - rb;
            bool s2 = (mem2[k] - thr2) > 0.f;
            cnt2[k] += s2 ? 1.f : 0.f;
            nm2[k] = __ballot_sync(0xffffffffu, s2);
        }

#pragma unroll
        for (int k = 0; k < 4; k++) { m1[k] = nm1[k]; m2[k] = nm2[k]; }
    }

    // avg_spikes = cnt/NUM_STEPS ; heads
    float4 wm = *reinterpret_cast<const float4*>(w_mean + 4 * lane);
    float4 ws = *reinterpret_cast<const float4*>(w_std  + 4 * lane);
    const float inv = 1.f / (float)NUM_STEPS;
    float a0 = cnt2[0] * inv, a1v = cnt2[1] * inv, a2v = cnt2[2] * inv, a3 = cnt2[3] * inv;
    float dm = a0 * wm.x + a1v * wm.y + a2v * wm.z + a3 * wm.w;
    float ds = a0 * ws.x + a1v * ws.y + a2v * ws.z + a3 * ws.w;
#pragma unroll
    for (int off = 16; off > 0; off >>= 1) {
        dm += __shfl_xor_sync(0xffffffffu, dm, off);
        ds += __shfl_xor_sync(0xffffffffu, ds, off);
    }
    if (lane == 0) {
        out[b] = tanhf(dm);
        float sig = 1.f / (1.f + expf(-(ds + 2.f)));
        out[B + b] = (MAX_STD - MIN_STD) * sig + MIN_STD;
    }
}

extern "C" void kernel_launch(void* const* d_in, const int* in_sizes, int n_in,
                              void* d_out, int out_size) {
    const float* state  = (const float*)d_in[0];
    const float* w_fc1  = (const float*)d_in[1];
    const float* w_rec1 = (const float*)d_in[2];
    const float* w_fc2  = (const float*)d_in[3];
    const float* w_rec2 = (const float*)d_in[4];
    const float* w_mean = (const float*)d_in[5];
    const float* w_std  = (const float*)d_in[6];
    const float* a1 = (const float*)d_in[7];
    const float* b1 = (const float*)d_in[8];
    const float* t1 = (const float*)d_in[9];
    const float* a2 = (const float*)d_in[10];
    const float* b2 = (const float*)d_in[11];
    const float* t2 = (const float*)d_in[12];
    float* out = (float*)d_out;

    int B = in_sizes[0] / STATE_DIM;

    snn_transpose_kernel<<<(HIDDEN * HIDDEN + 255) / 256, 256>>>(w_fc1, w_rec1, w_fc2, w_rec2);

    int total_threads = B * 32;                    // one warp per element
    int blocks = (total_threads + 255) / 256;
    snn_main_kernel<<<blocks, 256>>>(state, w_mean, w_std,
                                     a1, b1, t1, a2, b2, t2, out, B);
}

// round 2
// speedup vs baseline: 1.1212x; 1.1212x over previous
#include <cuda_runtime.h>
#include <cuda_bf16.h>
#include <math.h>

#define HIDDEN    128
#define STATE_DIM 6
#define NUM_STEPS 8
#define MAX_STD   2.0f
#define MIN_STD   0.1f

// Transposed weight scratch (allocation-free __device__ globals).
// Wt[j*HIDDEN + i] = W[i*HIDDEN + j]
__device__ float g_rec1t[HIDDEN * HIDDEN];
__device__ float g_fc2t [HIDDEN * HIDDEN];
__device__ float g_rec2t[HIDDEN * HIDDEN];
__device__ float g_fc1t [STATE_DIM * HIDDEN];

typedef unsigned long long u64;

__device__ __forceinline__ u64 pack2(float lo, float hi) {
    u64 r; asm("mov.b64 %0, {%1, %2};" : "=l"(r) : "f"(lo), "f"(hi)); return r;
}
__device__ __forceinline__ void unpack2(u64 v, float& lo, float& hi) {
    asm("mov.b64 {%0, %1}, %2;" : "=f"(lo), "=f"(hi) : "l"(v));
}
__device__ __forceinline__ u64 add2(u64 a, u64 b) {
    u64 r; asm("add.rn.f32x2 %0, %1, %2;" : "=l"(r) : "l"(a), "l"(b)); return r;
}
__device__ __forceinline__ u64 fma2(u64 a, u64 b, u64 c) {
    u64 r; asm("fma.rn.f32x2 %0, %1, %2, %3;" : "=l"(r) : "l"(a), "l"(b), "l"(c)); return r;
}

__global__ void snn_transpose_kernel(const float* __restrict__ w_fc1,
                                     const float* __restrict__ w_rec1,
                                     const float* __restrict__ w_fc2,
                                     const float* __restrict__ w_rec2) {
    int idx = blockIdx.x * blockDim.x + threadIdx.x;
    if (idx < HIDDEN * HIDDEN) {
        int i = idx / HIDDEN;
        int j = idx % HIDDEN;
        int t = j * HIDDEN + i;
        g_rec1t[t] = w_rec1[idx];
        g_fc2t [t] = w_fc2 [idx];
        g_rec2t[t] = w_rec2[idx];
        if (idx < HIDDEN * STATE_DIM) {
            int ii = idx / STATE_DIM;
            int d  = idx % STATE_DIM;
            g_fc1t[d * HIDDEN + ii] = w_fc1[idx];
        }
    }
}

// Sparse gather: for each set bit (word w, bit l) -> unit j = 4l+w, add
// Wt[j*128 + 4*lane .. +3] into packed accumulators. Byte offset of row j
// at this lane: j*512 + lane*16 = l*2048 + w*512 + lane*16.
__device__ __forceinline__ void gather2(const float* __restrict__ Wt,
                                        const unsigned m[4], int lane,
                                        u64& acc01, u64& acc23) {
    const char* base = reinterpret_cast<const char*>(Wt) + lane * 16;
#pragma unroll
    for (int w = 0; w < 4; w++) {
        unsigned mm = m[w];
        const char* bw = base + w * 512;
        while (mm) {
            int l = __ffs(mm) - 1;
            mm &= mm - 1;
            ulonglong2 v = *reinterpret_cast<const ulonglong2*>(bw + ((size_t)l << 11));
            acc01 = add2(acc01, v.x);
            acc23 = add2(acc23, v.y);
        }
    }
}

__global__ void __launch_bounds__(128)
snn_main_kernel(const float* __restrict__ state,
                const float* __restrict__ w_mean,
                const float* __restrict__ w_std,
                const float* __restrict__ p_a1, const float* __restrict__ p_b1,
                const float* __restrict__ p_t1, const float* __restrict__ p_a2,
                const float* __restrict__ p_b2, const float* __restrict__ p_t2,
                float* __restrict__ out, int B) {
    int gtid = blockIdx.x * blockDim.x + threadIdx.x;
    int b    = gtid >> 5;          // one warp per batch element
    int lane = threadIdx.x & 31;
    if (b >= B) return;

    const float a1 = fminf(fmaxf(*p_a1, 0.f), 1.f);
    const float b1 = fminf(fmaxf(*p_b1, 0.f), 1.f);
    const float a2 = fminf(fmaxf(*p_a2, 0.f), 1.f);
    const float b2 = fminf(fmaxf(*p_b2, 0.f), 1.f);
    const float thr1 = *p_t1;
    const float thr2 = *p_t2;

    const u64 a1p = pack2(a1, a1), b1p = pack2(b1, b1);
    const u64 a2p = pack2(a2, a2), b2p = pack2(b2, b2);
    const u64 nthr1p = pack2(-thr1, -thr1);
    const u64 nthr2p = pack2(-thr2, -thr2);

    // cur1_in = state[b] @ w_fc1.T  (constant across steps), packed
    u64 cur01 = 0, cur23 = 0;
#pragma unroll
    for (int d = 0; d < STATE_DIM; d++) {
        float sd = __ldg(state + (long)b * STATE_DIM + d);
        u64 sdp = pack2(sd, sd);
        ulonglong2 w = *reinterpret_cast<const ulonglong2*>(g_fc1t + d * HIDDEN + 4 * lane);
        cur01 = fma2(sdp, w.x, cur01);
        cur23 = fma2(sdp, w.y, cur23);
    }

    u64 syn1_01 = 0, syn1_23 = 0, mem1_01 = 0, mem1_23 = 0;
    u64 syn2_01 = 0, syn2_23 = 0, mem2_01 = 0, mem2_23 = 0;
    u64 spk1_01 = 0, spk1_23 = 0, spk2_01 = 0, spk2_23 = 0;   // {0,1} floats
    u64 cnt01 = 0, cnt23 = 0;
    unsigned m1[4] = {0u, 0u, 0u, 0u};
    unsigned m2[4] = {0u, 0u, 0u, 0u};

#pragma unroll
    for (int t = 0; t < NUM_STEPS; t++) {
        // ---------- layer 1 ----------
        u64 acc01 = cur01, acc23 = cur23;
        gather2(g_rec1t, m1, lane, acc01, acc23);      // spk1_prev @ w_rec1.T

        syn1_01 = fma2(a1p, syn1_01, acc01);
        syn1_23 = fma2(a1p, syn1_23, acc23);
        mem1_01 = fma2(b1p, mem1_01, syn1_01);
        mem1_23 = fma2(b1p, mem1_23, syn1_23);
        // reset-by-subtract using prev spike (== reset bit, detached)
        mem1_01 = fma2(spk1_01, nthr1p, mem1_01);
        mem1_23 = fma2(spk1_23, nthr1p, mem1_23);

        float f0, f1, f2, f3;
        unpack2(mem1_01, f0, f1);
        unpack2(mem1_23, f2, f3);
        bool s0 = f0 > thr1, s1 = f1 > thr1, s2 = f2 > thr1, s3 = f3 > thr1;
        unsigned nm1[4];
        nm1[0] = __ballot_sync(0xffffffffu, s0);
        nm1[1] = __ballot_sync(0xffffffffu, s1);
        nm1[2] = __ballot_sync(0xffffffffu, s2);
        nm1[3] = __ballot_sync(0xffffffffu, s3);
        spk1_01 = pack2(s0 ? 1.f : 0.f, s1 ? 1.f : 0.f);
        spk1_23 = pack2(s2 ? 1.f : 0.f, s3 ? 1.f : 0.f);

        // ---------- layer 2 ----------
        u64 acc2_01 = 0, acc2_23 = 0;
        gather2(g_fc2t,  nm1, lane, acc2_01, acc2_23); // spk1_new  @ w_fc2.T
        gather2(g_rec2t, m2,  lane, acc2_01, acc2_23); // spk2_prev @ w_rec2.T

        syn2_01 = fma2(a2p, syn2_01, acc2_01);
        syn2_23 = fma2(a2p, syn2_23, acc2_23);
        mem2_01 = fma2(b2p, mem2_01, syn2_01);
        mem2_23 = fma2(b2p, mem2_23, syn2_23);
        mem2_01 = fma2(spk2_01, nthr2p, mem2_01);
        mem2_23 = fma2(spk2_23, nthr2p, mem2_23);

        unpack2(mem2_01, f0, f1);
        unpack2(mem2_23, f2, f3);
        bool t0 = f0 > thr2, t1 = f1 > thr2, t2 = f2 > thr2, t3 = f3 > thr2;
        m2[0] = __ballot_sync(0xffffffffu, t0);
        m2[1] = __ballot_sync(0xffffffffu, t1);
        m2[2] = __ballot_sync(0xffffffffu, t2);
        m2[3] = __ballot_sync(0xffffffffu, t3);
        spk2_01 = pack2(t0 ? 1.f : 0.f, t1 ? 1.f : 0.f);
        spk2_23 = pack2(t2 ? 1.f : 0.f, t3 ? 1.f : 0.f);
        cnt01 = add2(cnt01, spk2_01);
        cnt23 = add2(cnt23, spk2_23);

        m1[0] = nm1[0]; m1[1] = nm1[1]; m1[2] = nm1[2]; m1[3] = nm1[3];
    }

    // heads: dot(avg_spikes, w_mean/w_std) + warp reduce
    float c0, c1, c2, c3;
    unpack2(cnt01, c0, c1);
    unpack2(cnt23, c2, c3);
    const float inv = 1.f / (float)NUM_STEPS;
    c0 *= inv; c1 *= inv; c2 *= inv; c3 *= inv;

    float4 wm = *reinterpret_cast<const float4*>(w_mean + 4 * lane);
    float4 ws = *reinterpret_cast<const float4*>(w_std  + 4 * lane);
    float dm = c0 * wm.x + c1 * wm.y + c2 * wm.z + c3 * wm.w;
    float ds = c0 * ws.x + c1 * ws.y + c2 * ws.z + c3 * ws.w;
#pragma unroll
    for (int off = 16; off > 0; off >>= 1) {
        dm += __shfl_xor_sync(0xffffffffu, dm, off);
        ds += __shfl_xor_sync(0xffffffffu, ds, off);
    }
    if (lane == 0) {
        out[b] = tanhf(dm);
        float sig = 1.f / (1.f + expf(-(ds + 2.f)));
        out[B + b] = (MAX_STD - MIN_STD) * sig + MIN_STD;
    }
}

extern "C" void kernel_launch(void* const* d_in, const int* in_sizes, int n_in,
                              void* d_out, int out_size) {
    const float* state  = (const float*)d_in[0];
    const float* w_fc1  = (const float*)d_in[1];
    const float* w_rec1 = (const float*)d_in[2];
    const float* w_fc2  = (const float*)d_in[3];
    const float* w_rec2 = (const float*)d_in[4];
    const float* w_mean = (const float*)d_in[5];
    const float* w_std  = (const float*)d_in[6];
    const float* a1 = (const float*)d_in[7];
    const float* b1 = (const float*)d_in[8];
    const float* t1 = (const float*)d_in[9];
    const float* a2 = (const float*)d_in[10];
    const float* b2 = (const float*)d_in[11];
    const float* t2 = (const float*)d_in[12];
    float* out = (float*)d_out;

    int B = in_sizes[0] / STATE_DIM;

    snn_transpose_kernel<<<(HIDDEN * HIDDEN + 255) / 256, 256>>>(w_fc1, w_rec1, w_fc2, w_rec2);

    int total_threads = B * 32;                    // one warp per element
    int blocks = (total_threads + 127) / 128;
    snn_main_kernel<<<blocks, 128>>>(state, w_mean, w_std,
                                     a1, b1, t1, a2, b2, t2, out, B);
}

// round 3
// speedup vs baseline: 1.1792x; 1.0517x over previous
#include <cuda_runtime.h>
#include <cuda_bf16.h>
#include <math.h>

#define HIDDEN    128
#define STATE_DIM 6
#define NUM_STEPS 8
#define MAX_STD   2.0f
#define MIN_STD   0.1f

// Transposed weight scratch (allocation-free __device__ globals).
// Wt[j*HIDDEN + i] = W[i*HIDDEN + j]
__device__ float g_rec1t[HIDDEN * HIDDEN];
__device__ float g_fc2t [HIDDEN * HIDDEN];
__device__ float g_rec2t[HIDDEN * HIDDEN];
__device__ float g_fc1t [STATE_DIM * HIDDEN];

typedef unsigned long long u64;

__device__ __forceinline__ u64 pack2(float lo, float hi) {
    u64 r; asm("mov.b64 %0, {%1, %2};" : "=l"(r) : "f"(lo), "f"(hi)); return r;
}
__device__ __forceinline__ void unpack2(u64 v, float& lo, float& hi) {
    asm("mov.b64 {%0, %1}, %2;" : "=f"(lo), "=f"(hi) : "l"(v));
}
__device__ __forceinline__ u64 add2(u64 a, u64 b) {
    u64 r; asm("add.rn.f32x2 %0, %1, %2;" : "=l"(r) : "l"(a), "l"(b)); return r;
}
__device__ __forceinline__ u64 mul2(u64 a, u64 b) {
    u64 r; asm("mul.rn.f32x2 %0, %1, %2;" : "=l"(r) : "l"(a), "l"(b)); return r;
}
__device__ __forceinline__ u64 fma2(u64 a, u64 b, u64 c) {
    u64 r; asm("fma.rn.f32x2 %0, %1, %2, %3;" : "=l"(r) : "l"(a), "l"(b), "l"(c)); return r;
}
// Single-SASS FLO (position of most-significant set bit, 0-based).
__device__ __forceinline__ unsigned bfind(unsigned x) {
    unsigned r; asm("bfind.u32 %0, %1;" : "=r"(r) : "r"(x)); return r;
}

__global__ void snn_transpose_kernel(const float* __restrict__ w_fc1,
                                     const float* __restrict__ w_rec1,
                                     const float* __restrict__ w_fc2,
                                     const float* __restrict__ w_rec2) {
    int idx = blockIdx.x * blockDim.x + threadIdx.x;
    if (idx < HIDDEN * HIDDEN) {
        int i = idx / HIDDEN;
        int j = idx % HIDDEN;
        int t = j * HIDDEN + i;
        g_rec1t[t] = w_rec1[idx];
        g_fc2t [t] = w_fc2 [idx];
        g_rec2t[t] = w_rec2[idx];
        if (idx < HIDDEN * STATE_DIM) {
            int ii = idx / STATE_DIM;
            int d  = idx % STATE_DIM;
            g_fc1t[d * HIDDEN + ii] = w_fc1[idx];
        }
    }
}

// Sparse gather: for each set bit (word w, bit l) -> unit j = 4l+w, add
// Wt[j*128 + 4*lane .. +3] into the packed accumulators.
// Byte offset at this lane: l*2048 + w*512 + lane*16.
// MSB scan: bfind (1 FLO) + subtract-clear (SHF+IADD) + IMAD.WIDE address.
__device__ __forceinline__ void gather2(const float* __restrict__ Wt,
                                        const unsigned m[4], int lane,
                                        u64& a01, u64& a23) {
    const char* base = reinterpret_cast<const char*>(Wt) + lane * 16;
#pragma unroll
    for (int w = 0; w < 4; w++) {
        unsigned mm = m[w];
        const char* bw = base + w * 512;
        while (mm) {
            unsigned l = bfind(mm);          // MSB position
            mm -= (1u << l);                 // clear it
            ulonglong2 v = *reinterpret_cast<const ulonglong2*>(bw + l * 2048u);
            a01 = add2(a01, v.x);
            a23 = add2(a23, v.y);
        }
    }
}

__global__ void __launch_bounds__(128)
snn_main_kernel(const float* __restrict__ state,
                const float* __restrict__ w_mean,
                const float* __restrict__ w_std,
                const float* __restrict__ p_a1, const float* __restrict__ p_b1,
                const float* __restrict__ p_t1, const float* __restrict__ p_a2,
                const float* __restrict__ p_b2, const float* __restrict__ p_t2,
                float* __restrict__ out, int B) {
    int gtid = blockIdx.x * blockDim.x + threadIdx.x;
    int b    = gtid >> 5;          // one warp per batch element
    int lane = threadIdx.x & 31;
    if (b >= B) return;

    const float a1 = fminf(fmaxf(*p_a1, 0.f), 1.f);
    const float b1 = fminf(fmaxf(*p_b1, 0.f), 1.f);
    const float a2 = fminf(fmaxf(*p_a2, 0.f), 1.f);
    const float b2 = fminf(fmaxf(*p_b2, 0.f), 1.f);
    const float thr1 = *p_t1;
    const float thr2 = *p_t2;

    const u64 a1p = pack2(a1, a1), b1p = pack2(b1, b1);
    const u64 a2p = pack2(a2, a2), b2p = pack2(b2, b2);
    const u64 nthr1p = pack2(-thr1, -thr1);
    const u64 nthr2p = pack2(-thr2, -thr2);

    // cur1_in = state[b] @ w_fc1.T  (constant across steps), packed
    u64 cur01 = 0, cur23 = 0;
#pragma unroll
    for (int d = 0; d < STATE_DIM; d++) {
        float sd = __ldg(state + (long)b * STATE_DIM + d);
        u64 sdp = pack2(sd, sd);
        ulonglong2 w = *reinterpret_cast<const ulonglong2*>(g_fc1t + d * HIDDEN + 4 * lane);
        cur01 = fma2(sdp, w.x, cur01);
        cur23 = fma2(sdp, w.y, cur23);
    }

    u64 syn1_01 = 0, syn1_23 = 0, mem1_01 = 0, mem1_23 = 0;
    u64 syn2_01 = 0, syn2_23 = 0, mem2_01 = 0, mem2_23 = 0;
    u64 spk1_01 = 0, spk1_23 = 0, spk2_01 = 0, spk2_23 = 0;   // {0,1} floats
    u64 cnt01 = 0, cnt23 = 0;
    unsigned m1[4] = {0u, 0u, 0u, 0u};
    unsigned m2[4] = {0u, 0u, 0u, 0u};

#pragma unroll
    for (int t = 0; t < NUM_STEPS; t++) {
        // ---------- layer 1 ----------
        // syn1 = a1*syn1 + cur1; gather accumulates straight into syn1
        syn1_01 = fma2(a1p, syn1_01, cur01);
        syn1_23 = fma2(a1p, syn1_23, cur23);
        gather2(g_rec1t, m1, lane, syn1_01, syn1_23);   // + spk1_prev @ w_rec1.T

        mem1_01 = fma2(b1p, mem1_01, syn1_01);
        mem1_23 = fma2(b1p, mem1_23, syn1_23);
        mem1_01 = fma2(spk1_01, nthr1p, mem1_01);       // reset-by-subtract (prev spike)
        mem1_23 = fma2(spk1_23, nthr1p, mem1_23);

        float f0, f1, f2, f3;
        unpack2(mem1_01, f0, f1);
        unpack2(mem1_23, f2, f3);
        bool s0 = f0 > thr1, s1 = f1 > thr1, s2 = f2 > thr1, s3 = f3 > thr1;
        unsigned nm1[4];
        nm1[0] = __ballot_sync(0xffffffffu, s0);
        nm1[1] = __ballot_sync(0xffffffffu, s1);
        nm1[2] = __ballot_sync(0xffffffffu, s2);
        nm1[3] = __ballot_sync(0xffffffffu, s3);
        spk1_01 = pack2(s0 ? 1.f : 0.f, s1 ? 1.f : 0.f);
        spk1_23 = pack2(s2 ? 1.f : 0.f, s3 ? 1.f : 0.f);

        // ---------- layer 2 ----------
        syn2_01 = mul2(a2p, syn2_01);
        syn2_23 = mul2(a2p, syn2_23);
        gather2(g_fc2t,  nm1, lane, syn2_01, syn2_23);  // + spk1_new  @ w_fc2.T
        gather2(g_rec2t, m2,  lane, syn2_01, syn2_23);  // + spk2_prev @ w_rec2.T

        mem2_01 = fma2(b2p, mem2_01, syn2_01);
        mem2_23 = fma2(b2p, mem2_23, syn2_23);
        mem2_01 = fma2(spk2_01, nthr2p, mem2_01);
        mem2_23 = fma2(spk2_23, nthr2p, mem2_23);

        unpack2(mem2_01, f0, f1);
        unpack2(mem2_23, f2, f3);
        bool t0 = f0 > thr2, t1 = f1 > thr2, t2 = f2 > thr2, t3 = f3 > thr2;
        m2[0] = __ballot_sync(0xffffffffu, t0);
        m2[1] = __ballot_sync(0xffffffffu, t1);
        m2[2] = __ballot_sync(0xffffffffu, t2);
        m2[3] = __ballot_sync(0xffffffffu, t3);
        spk2_01 = pack2(t0 ? 1.f : 0.f, t1 ? 1.f : 0.f);
        spk2_23 = pack2(t2 ? 1.f : 0.f, t3 ? 1.f : 0.f);
        cnt01 = add2(cnt01, spk2_01);
        cnt23 = add2(cnt23, spk2_23);

        m1[0] = nm1[0]; m1[1] = nm1[1]; m1[2] = nm1[2]; m1[3] = nm1[3];
    }

    // heads: dot(avg_spikes, w_mean/w_std) + warp reduce
    float c0, c1, c2, c3;
    unpack2(cnt01, c0, c1);
    unpack2(cnt23, c2, c3);
    const float inv = 1.f / (float)NUM_STEPS;
    c0 *= inv; c1 *= inv; c2 *= inv; c3 *= inv;

    float4 wm = *reinterpret_cast<const float4*>(w_mean + 4 * lane);
    float4 ws = *reinterpret_cast<const float4*>(w_std  + 4 * lane);
    float dm = fmaf(c0, wm.x, fmaf(c1, wm.y, fmaf(c2, wm.z, c3 * wm.w)));
    float ds = fmaf(c0, ws.x, fmaf(c1, ws.y, fmaf(c2, ws.z, c3 * ws.w)));
#pragma unroll
    for (int off = 16; off > 0; off >>= 1) {
        dm += __shfl_xor_sync(0xffffffffu, dm, off);
        ds += __shfl_xor_sync(0xffffffffu, ds, off);
    }
    if (lane == 0) {
        out[b] = tanhf(dm);
        float sig = 1.f / (1.f + expf(-(ds + 2.f)));
        out[B + b] = (MAX_STD - MIN_STD) * sig + MIN_STD;
    }
}

extern "C" void kernel_launch(void* const* d_in, const int* in_sizes, int n_in,
                              void* d_out, int out_size) {
    const float* state  = (const float*)d_in[0];
    const float* w_fc1  = (const float*)d_in[1];
    const float* w_rec1 = (const float*)d_in[2];
    const float* w_fc2  = (const float*)d_in[3];
    const float* w_rec2 = (const float*)d_in[4];
    const float* w_mean = (const float*)d_in[5];
    const float* w_std  = (const float*)d_in[6];
    const float* a1 = (const float*)d_in[7];
    const float* b1 = (const float*)d_in[8];
    const float* t1 = (const float*)d_in[9];
    const float* a2 = (const float*)d_in[10];
    const float* b2 = (const float*)d_in[11];
    const float* t2 = (const float*)d_in[12];
    float* out = (float*)d_out;

    int B = in_sizes[0] / STATE_DIM;

    snn_transpose_kernel<<<(HIDDEN * HIDDEN + 255) / 256, 256>>>(w_fc1, w_rec1, w_fc2, w_rec2);

    int total_threads = B * 32;                    // one warp per element
    int blocks = (total_threads + 127) / 128;
    snn_main_kernel<<<blocks, 128>>>(state, w_mean, w_std,
                                     a1, b1, t1, a2, b2, t2, out, B);
}

// round 4
// speedup vs baseline: 1.3212x; 1.1204x over previous
#include <cuda_runtime.h>
#include <cuda_bf16.h>
#include <math.h>

#define HIDDEN    128
#define STATE_DIM 6
#define NUM_STEPS 8
#define MAX_STD   2.0f
#define MIN_STD   0.1f

// Transposed weight scratch (allocation-free __device__ globals).
// Wt[j*HIDDEN + i] = W[i*HIDDEN + j]
__device__ float g_rec1t[HIDDEN * HIDDEN];
__device__ float g_fc2t [HIDDEN * HIDDEN];
__device__ float g_rec2t[HIDDEN * HIDDEN];
__device__ float g_fc1t [STATE_DIM * HIDDEN];

typedef unsigned long long u64;

__device__ __forceinline__ u64 pack2(float lo, float hi) {
    u64 r; asm("mov.b64 %0, {%1, %2};" : "=l"(r) : "f"(lo), "f"(hi)); return r;
}
__device__ __forceinline__ void unpack2(u64 v, float& lo, float& hi) {
    asm("mov.b64 {%0, %1}, %2;" : "=f"(lo), "=f"(hi) : "l"(v));
}
__device__ __forceinline__ u64 add2(u64 a, u64 b) {
    u64 r; asm("add.rn.f32x2 %0, %1, %2;" : "=l"(r) : "l"(a), "l"(b)); return r;
}
__device__ __forceinline__ u64 mul2(u64 a, u64 b) {
    u64 r; asm("mul.rn.f32x2 %0, %1, %2;" : "=l"(r) : "l"(a), "l"(b)); return r;
}
__device__ __forceinline__ u64 fma2(u64 a, u64 b, u64 c) {
    u64 r; asm("fma.rn.f32x2 %0, %1, %2, %3;" : "=l"(r) : "l"(a), "l"(b), "l"(c)); return r;
}
// Single-SASS FLO (position of most-significant set bit, 0-based).
__device__ __forceinline__ unsigned bfind(unsigned x) {
    unsigned r; asm("bfind.u32 %0, %1;" : "=r"(r) : "r"(x)); return r;
}

__global__ void snn_transpose_kernel(const float* __restrict__ w_fc1,
                                     const float* __restrict__ w_rec1,
                                     const float* __restrict__ w_fc2,
                                     const float* __restrict__ w_rec2) {
    int idx = blockIdx.x * blockDim.x + threadIdx.x;
    if (idx < HIDDEN * HIDDEN) {
        int i = idx / HIDDEN;
        int j = idx % HIDDEN;
        int t = j * HIDDEN + i;
        g_rec1t[t] = w_rec1[idx];
        g_fc2t [t] = w_fc2 [idx];
        g_rec2t[t] = w_rec2[idx];
        if (idx < HIDDEN * STATE_DIM) {
            int ii = idx / STATE_DIM;
            int d  = idx % STATE_DIM;
            g_fc1t[d * HIDDEN + ii] = w_fc1[idx];
        }
    }
}

// Sparse gather: for each set bit (word w, bit l) -> unit j = 4l+w, add
// Wt[j*128 + 4*lane .. +3] into the packed accumulators.
// Byte offset at this lane: l*2048 + w*512 + lane*16.
__device__ __forceinline__ void gather2(const float* __restrict__ Wt,
                                        const unsigned m[4], int lane,
                                        u64& a01, u64& a23) {
    const char* base = reinterpret_cast<const char*>(Wt) + lane * 16;
#pragma unroll
    for (int w = 0; w < 4; w++) {
        unsigned mm = m[w];
        const char* bw = base + w * 512;
        while (mm) {
            unsigned l = bfind(mm);          // MSB position
            mm -= (1u << l);                 // clear it
            ulonglong2 v = *reinterpret_cast<const ulonglong2*>(bw + l * 2048u);
            a01 = add2(a01, v.x);
            a23 = add2(a23, v.y);
        }
    }
}

__global__ void __launch_bounds__(128)
snn_main_kernel(const float* __restrict__ state,
                const float* __restrict__ w_mean,
                const float* __restrict__ w_std,
                const float* __restrict__ p_a1, const float* __restrict__ p_b1,
                const float* __restrict__ p_t1, const float* __restrict__ p_a2,
                const float* __restrict__ p_b2, const float* __restrict__ p_t2,
                float* __restrict__ out, int B) {
    int gtid = blockIdx.x * blockDim.x + threadIdx.x;
    int b    = gtid >> 5;          // one warp per batch element
    int lane = threadIdx.x & 31;
    if (b >= B) return;

    const float a1 = fminf(fmaxf(*p_a1, 0.f), 1.f);
    const float b1 = fminf(fmaxf(*p_b1, 0.f), 1.f);
    const float a2 = fminf(fmaxf(*p_a2, 0.f), 1.f);
    const float b2 = fminf(fmaxf(*p_b2, 0.f), 1.f);
    const float thr1 = *p_t1;
    const float thr2 = *p_t2;

    const u64 a1p = pack2(a1, a1), b1p = pack2(b1, b1);
    const u64 a2p = pack2(a2, a2), b2p = pack2(b2, b2);
    const u64 nthr1p = pack2(-thr1, -thr1);
    const u64 nthr2p = pack2(-thr2, -thr2);

    // cur1_in = state[b] @ w_fc1.T  (constant across steps), packed
    u64 cur01 = 0, cur23 = 0;
#pragma unroll
    for (int d = 0; d < STATE_DIM; d++) {
        float sd = __ldg(state + (long)b * STATE_DIM + d);
        u64 sdp = pack2(sd, sd);
        ulonglong2 w = *reinterpret_cast<const ulonglong2*>(g_fc1t + d * HIDDEN + 4 * lane);
        cur01 = fma2(sdp, w.x, cur01);
        cur23 = fma2(sdp, w.y, cur23);
    }

    u64 syn1_01 = 0, syn1_23 = 0, mem1_01 = 0, mem1_23 = 0;
    u64 syn2_01 = 0, syn2_23 = 0, mem2_01 = 0, mem2_23 = 0;
    u64 spk1_01 = 0, spk1_23 = 0, spk2_01 = 0, spk2_23 = 0;   // {0,1} floats
    u64 cnt01 = 0, cnt23 = 0;
    unsigned m1[4] = {0u, 0u, 0u, 0u};
    unsigned m2[4] = {0u, 0u, 0u, 0u};
    bool live2 = false;   // warp-uniform: layer-2 spiked on previous step

#pragma unroll
    for (int t = 0; t < NUM_STEPS; t++) {
        // ---------- layer 1 ----------
        // syn1 = a1*syn1 + cur1; gather accumulates straight into syn1
        syn1_01 = fma2(a1p, syn1_01, cur01);
        syn1_23 = fma2(a1p, syn1_23, cur23);
        gather2(g_rec1t, m1, lane, syn1_01, syn1_23);   // + spk1_prev @ w_rec1.T

        mem1_01 = fma2(b1p, mem1_01, syn1_01);
        mem1_23 = fma2(b1p, mem1_23, syn1_23);
        mem1_01 = fma2(spk1_01, nthr1p, mem1_01);       // reset-by-subtract (prev spike)
        mem1_23 = fma2(spk1_23, nthr1p, mem1_23);

        float f0, f1, f2, f3;
        unpack2(mem1_01, f0, f1);
        unpack2(mem1_23, f2, f3);
        bool s0 = f0 > thr1, s1 = f1 > thr1, s2 = f2 > thr1, s3 = f3 > thr1;
        m1[0] = __ballot_sync(0xffffffffu, s0);
        m1[1] = __ballot_sync(0xffffffffu, s1);
        m1[2] = __ballot_sync(0xffffffffu, s2);
        m1[3] = __ballot_sync(0xffffffffu, s3);
        spk1_01 = pack2(s0 ? 1.f : 0.f, s1 ? 1.f : 0.f);
        spk1_23 = pack2(s2 ? 1.f : 0.f, s3 ? 1.f : 0.f);

        // ---------- layer 2 ----------
        syn2_01 = mul2(a2p, syn2_01);
        syn2_23 = mul2(a2p, syn2_23);
        gather2(g_fc2t, m1, lane, syn2_01, syn2_23);    // + spk1_new @ w_fc2.T
        if (live2) {
            // rare: previous step had layer-2 spikes
            gather2(g_rec2t, m2, lane, syn2_01, syn2_23);   // + spk2_prev @ w_rec2.T
        }

        mem2_01 = fma2(b2p, mem2_01, syn2_01);
        mem2_23 = fma2(b2p, mem2_23, syn2_23);
        if (live2) {
            mem2_01 = fma2(spk2_01, nthr2p, mem2_01);   // reset-by-subtract (prev spike)
            mem2_23 = fma2(spk2_23, nthr2p, mem2_23);
        }

        unpack2(mem2_01, f0, f1);
        unpack2(mem2_23, f2, f3);
        bool t0 = f0 > thr2, t1 = f1 > thr2, t2 = f2 > thr2, t3 = f3 > thr2;
        if (__any_sync(0xffffffffu, t0 | t1 | t2 | t3)) {
            // rare path: record layer-2 spikes
            m2[0] = __ballot_sync(0xffffffffu, t0);
            m2[1] = __ballot_sync(0xffffffffu, t1);
            m2[2] = __ballot_sync(0xffffffffu, t2);
            m2[3] = __ballot_sync(0xffffffffu, t3);
            spk2_01 = pack2(t0 ? 1.f : 0.f, t1 ? 1.f : 0.f);
            spk2_23 = pack2(t2 ? 1.f : 0.f, t3 ? 1.f : 0.f);
            cnt01 = add2(cnt01, spk2_01);
            cnt23 = add2(cnt23, spk2_23);
            live2 = true;
        } else {
            // common path: no spikes anywhere in this warp's layer 2.
            // m2/spk2 are stale but only read under live2 == true.
            live2 = false;
        }
    }

    // heads: dot(avg_spikes, w_mean/w_std) + warp reduce
    float c0, c1, c2, c3;
    unpack2(cnt01, c0, c1);
    unpack2(cnt23, c2, c3);
    const float inv = 1.f / (float)NUM_STEPS;
    c0 *= inv; c1 *= inv; c2 *= inv; c3 *= inv;

    float4 wm = *reinterpret_cast<const float4*>(w_mean + 4 * lane);
    float4 ws = *reinterpret_cast<const float4*>(w_std  + 4 * lane);
    float dm = fmaf(c0, wm.x, fmaf(c1, wm.y, fmaf(c2, wm.z, c3 * wm.w)));
    float ds = fmaf(c0, ws.x, fmaf(c1, ws.y, fmaf(c2, ws.z, c3 * ws.w)));
#pragma unroll
    for (int off = 16; off > 0; off >>= 1) {
        dm += __shfl_xor_sync(0xffffffffu, dm, off);
        ds += __shfl_xor_sync(0xffffffffu, ds, off);
    }
    if (lane == 0) {
        out[b] = tanhf(dm);
        float sig = 1.f / (1.f + expf(-(ds + 2.f)));
        out[B + b] = (MAX_STD - MIN_STD) * sig + MIN_STD;
    }
}

extern "C" void kernel_launch(void* const* d_in, const int* in_sizes, int n_in,
                              void* d_out, int out_size) {
    const float* state  = (const float*)d_in[0];
    const float* w_fc1  = (const float*)d_in[1];
    const float* w_rec1 = (const float*)d_in[2];
    const float* w_fc2  = (const float*)d_in[3];
    const float* w_rec2 = (const float*)d_in[4];
    const float* w_mean = (const float*)d_in[5];
    const float* w_std  = (const float*)d_in[6];
    const float* a1 = (const float*)d_in[7];
    const float* b1 = (const float*)d_in[8];
    const float* t1 = (const float*)d_in[9];
    const float* a2 = (const float*)d_in[10];
    const float* b2 = (const float*)d_in[11];
    const float* t2 = (const float*)d_in[12];
    float* out = (float*)d_out;

    int B = in_sizes[0] / STATE_DIM;

    snn_transpose_kernel<<<(HIDDEN * HIDDEN + 255) / 256, 256>>>(w_fc1, w_rec1, w_fc2, w_rec2);

    int total_threads = B * 32;                    // one warp per element
    int blocks = (total_threads + 127) / 128;
    snn_main_kernel<<<blocks, 128>>>(state, w_mean, w_std,
                                     a1, b1, t1, a2, b2, t2, out, B);
}

// round 5
// speedup vs baseline: 1.6615x; 1.2576x over previous
#include <cuda_runtime.h>
#include <cuda_bf16.h>
#include <math.h>

#define HIDDEN    128
#define STATE_DIM 6
#define NUM_STEPS 8
#define MAX_STD   2.0f
#define MIN_STD   0.1f

// Combined interleaved table: row j (unit j) = 256 floats (1024 B).
// For lane L, k=0..3:  c12[j*256 + 8L + k]     = w_fc2 [(4L+k)*128 + j]
//                      c12[j*256 + 8L + 4 + k] = w_rec1[(4L+k)*128 + j]
__device__ float g_c12  [HIDDEN * 256];
__device__ float g_rec2t[HIDDEN * HIDDEN];   // rec2t[j*128 + i] = w_rec2[i*128 + j]
__device__ float g_fc1t [STATE_DIM * HIDDEN];

typedef unsigned long long u64;

__device__ __forceinline__ u64 pack2(float lo, float hi) {
    u64 r; asm("mov.b64 %0, {%1, %2};" : "=l"(r) : "f"(lo), "f"(hi)); return r;
}
__device__ __forceinline__ void unpack2(u64 v, float& lo, float& hi) {
    asm("mov.b64 {%0, %1}, %2;" : "=f"(lo), "=f"(hi) : "l"(v));
}
__device__ __forceinline__ u64 add2(u64 a, u64 b) {
    u64 r; asm("add.rn.f32x2 %0, %1, %2;" : "=l"(r) : "l"(a), "l"(b)); return r;
}
__device__ __forceinline__ u64 mul2(u64 a, u64 b) {
    u64 r; asm("mul.rn.f32x2 %0, %1, %2;" : "=l"(r) : "l"(a), "l"(b)); return r;
}
__device__ __forceinline__ u64 fma2(u64 a, u64 b, u64 c) {
    u64 r; asm("fma.rn.f32x2 %0, %1, %2, %3;" : "=l"(r) : "l"(a), "l"(b), "l"(c)); return r;
}
__device__ __forceinline__ unsigned bfind(unsigned x) {
    unsigned r; asm("bfind.u32 %0, %1;" : "=r"(r) : "r"(x)); return r;
}

__global__ void snn_transpose_kernel(const float* __restrict__ w_fc1,
                                     const float* __restrict__ w_rec1,
                                     const float* __restrict__ w_fc2,
                                     const float* __restrict__ w_rec2) {
    int idx = blockIdx.x * blockDim.x + threadIdx.x;   // over 128*128
    if (idx < HIDDEN * HIDDEN) {
        int i = idx / HIDDEN;      // output unit
        int j = idx % HIDDEN;      // input unit (row of table)
        int L = i >> 2, k = i & 3;
        g_c12[j * 256 + 8 * L + k]     = w_fc2 [idx];
        g_c12[j * 256 + 8 * L + 4 + k] = w_rec1[idx];
        g_rec2t[j * HIDDEN + i] = w_rec2[idx];
        if (idx < HIDDEN * STATE_DIM) {
            int ii = idx / STATE_DIM;
            int d  = idx % STATE_DIM;
            g_fc1t[d * HIDDEN + ii] = w_fc1[idx];
        }
    }
}

// Fused gather over mask m (layer-1 spikes): for each set bit (w,l) -> unit j=4l+w,
// add fc2 row into s01/s23 (syn2, used this step) and rec1 row into r01/r23
// (pending contribution to next step's syn1).
// Byte offset of row j at lane L: j*1024 + L*32 = l*4096 + w*1024 + L*32.
__device__ __forceinline__ void gather_fused(const unsigned m[4], int lane,
                                             u64& s01, u64& s23,
                                             u64& r01, u64& r23) {
    const char* base = reinterpret_cast<const char*>(g_c12) + lane * 32;
#pragma unroll
    for (int w = 0; w < 4; w++) {
        unsigned mm = m[w];
        const char* bw = base + w * 1024;
        while (mm) {
            unsigned l = bfind(mm);
            mm -= (1u << l);
            const char* p = bw + l * 4096u;
            ulonglong2 vf = *reinterpret_cast<const ulonglong2*>(p);        // fc2
            ulonglong2 vr = *reinterpret_cast<const ulonglong2*>(p + 16);   // rec1
            s01 = add2(s01, vf.x);
            s23 = add2(s23, vf.y);
            r01 = add2(r01, vr.x);
            r23 = add2(r23, vr.y);
        }
    }
}

// Plain gather (rare layer-2 recurrent path), 16B/lane rows.
__device__ __forceinline__ void gather2(const float* __restrict__ Wt,
                                        const unsigned m[4], int lane,
                                        u64& a01, u64& a23) {
    const char* base = reinterpret_cast<const char*>(Wt) + lane * 16;
#pragma unroll
    for (int w = 0; w < 4; w++) {
        unsigned mm = m[w];
        const char* bw = base + w * 512;
        while (mm) {
            unsigned l = bfind(mm);
            mm -= (1u << l);
            ulonglong2 v = *reinterpret_cast<const ulonglong2*>(bw + l * 2048u);
            a01 = add2(a01, v.x);
            a23 = add2(a23, v.y);
        }
    }
}

__global__ void __launch_bounds__(128)
snn_main_kernel(const float* __restrict__ state,
                const float* __restrict__ w_mean,
                const float* __restrict__ w_std,
                const float* __restrict__ p_a1, const float* __restrict__ p_b1,
                const float* __restrict__ p_t1, const float* __restrict__ p_a2,
                const float* __restrict__ p_b2, const float* __restrict__ p_t2,
                float* __restrict__ out, int B) {
    int gtid = blockIdx.x * blockDim.x + threadIdx.x;
    int b    = gtid >> 5;          // one warp per batch element
    int lane = threadIdx.x & 31;
    if (b >= B) return;

    const float a1 = fminf(fmaxf(*p_a1, 0.f), 1.f);
    const float b1 = fminf(fmaxf(*p_b1, 0.f), 1.f);
    const float a2 = fminf(fmaxf(*p_a2, 0.f), 1.f);
    const float b2 = fminf(fmaxf(*p_b2, 0.f), 1.f);
    const float thr1 = *p_t1;
    const float thr2 = *p_t2;

    const u64 a1p = pack2(a1, a1), b1p = pack2(b1, b1);
    const u64 a2p = pack2(a2, a2), b2p = pack2(b2, b2);
    const u64 nthr1p = pack2(-thr1, -thr1);
    const u64 nthr2p = pack2(-thr2, -thr2);

    // cur1_in = state[b] @ w_fc1.T (constant across steps), packed
    u64 cur01 = 0, cur23 = 0;
#pragma unroll
    for (int d = 0; d < STATE_DIM; d++) {
        float sd = __ldg(state + (long)b * STATE_DIM + d);
        u64 sdp = pack2(sd, sd);
        ulonglong2 w = *reinterpret_cast<const ulonglong2*>(g_fc1t + d * HIDDEN + 4 * lane);
        cur01 = fma2(sdp, w.x, cur01);
        cur23 = fma2(sdp, w.y, cur23);
    }

    u64 syn1_01 = 0, syn1_23 = 0, mem1_01 = 0, mem1_23 = 0;
    u64 syn2_01 = 0, syn2_23 = 0, mem2_01 = 0, mem2_23 = 0;
    u64 spk1_01 = 0, spk1_23 = 0, spk2_01 = 0, spk2_23 = 0;   // {0,1} floats
    u64 cnt01 = 0, cnt23 = 0;
    u64 r1p01 = 0, r1p23 = 0;      // pending rec1 contribution (from prev step's spikes)
    unsigned m2[4] = {0u, 0u, 0u, 0u};
    bool live2 = false;            // warp-uniform: layer-2 spiked on previous step

#pragma unroll
    for (int t = 0; t < NUM_STEPS; t++) {
        // ---------- layer 1 ----------
        // syn1 = a1*syn1 + cur1 + (spk1_prev @ w_rec1.T, pre-gathered last step)
        syn1_01 = fma2(a1p, syn1_01, cur01);
        syn1_23 = fma2(a1p, syn1_23, cur23);
        syn1_01 = add2(syn1_01, r1p01);
        syn1_23 = add2(syn1_23, r1p23);

        mem1_01 = fma2(b1p, mem1_01, syn1_01);
        mem1_23 = fma2(b1p, mem1_23, syn1_23);
        mem1_01 = fma2(spk1_01, nthr1p, mem1_01);       // reset-by-subtract (prev spike)
        mem1_23 = fma2(spk1_23, nthr1p, mem1_23);

        float f0, f1, f2, f3;
        unpack2(mem1_01, f0, f1);
        unpack2(mem1_23, f2, f3);
        bool s0 = f0 > thr1, s1 = f1 > thr1, s2 = f2 > thr1, s3 = f3 > thr1;
        unsigned m1[4];
        m1[0] = __ballot_sync(0xffffffffu, s0);
        m1[1] = __ballot_sync(0xffffffffu, s1);
        m1[2] = __ballot_sync(0xffffffffu, s2);
        m1[3] = __ballot_sync(0xffffffffu, s3);
        spk1_01 = pack2(s0 ? 1.f : 0.f, s1 ? 1.f : 0.f);
        spk1_23 = pack2(s2 ? 1.f : 0.f, s3 ? 1.f : 0.f);

        // ---------- layer 2 + pre-gather of next step's rec1 ----------
        syn2_01 = mul2(a2p, syn2_01);
        syn2_23 = mul2(a2p, syn2_23);
        r1p01 = 0; r1p23 = 0;
        // one pass over m1 bits: fc2 -> syn2 (now), rec1 -> r1p (next step)
        gather_fused(m1, lane, syn2_01, syn2_23, r1p01, r1p23);
        if (live2) {
            gather2(g_rec2t, m2, lane, syn2_01, syn2_23);   // + spk2_prev @ w_rec2.T
        }

        mem2_01 = fma2(b2p, mem2_01, syn2_01);
        mem2_23 = fma2(b2p, mem2_23, syn2_23);
        if (live2) {
            mem2_01 = fma2(spk2_01, nthr2p, mem2_01);
            mem2_23 = fma2(spk2_23, nthr2p, mem2_23);
        }

        unpack2(mem2_01, f0, f1);
        unpack2(mem2_23, f2, f3);
        bool t0 = f0 > thr2, t1 = f1 > thr2, t2 = f2 > thr2, t3 = f3 > thr2;
        if (__any_sync(0xffffffffu, t0 | t1 | t2 | t3)) {
            // rare path: record layer-2 spikes
            m2[0] = __ballot_sync(0xffffffffu, t0);
            m2[1] = __ballot_sync(0xffffffffu, t1);
            m2[2] = __ballot_sync(0xffffffffu, t2);
            m2[3] = __ballot_sync(0xffffffffu, t3);
            spk2_01 = pack2(t0 ? 1.f : 0.f, t1 ? 1.f : 0.f);
            spk2_23 = pack2(t2 ? 1.f : 0.f, t3 ? 1.f : 0.f);
            cnt01 = add2(cnt01, spk2_01);
            cnt23 = add2(cnt23, spk2_23);
            live2 = true;
        } else {
            live2 = false;   // m2/spk2 stale but only read under live2
        }
    }

    // heads: dot(avg_spikes, w_mean/w_std) + warp reduce
    float c0, c1, c2, c3;
    unpack2(cnt01, c0, c1);
    unpack2(cnt23, c2, c3);
    const float inv = 1.f / (float)NUM_STEPS;
    c0 *= inv; c1 *= inv; c2 *= inv; c3 *= inv;

    float4 wm = *reinterpret_cast<const float4*>(w_mean + 4 * lane);
    float4 ws = *reinterpret_cast<const float4*>(w_std  + 4 * lane);
    float dm = fmaf(c0, wm.x, fmaf(c1, wm.y, fmaf(c2, wm.z, c3 * wm.w)));
    float ds = fmaf(c0, ws.x, fmaf(c1, ws.y, fmaf(c2, ws.z, c3 * ws.w)));
#pragma unroll
    for (int off = 16; off > 0; off >>= 1) {
        dm += __shfl_xor_sync(0xffffffffu, dm, off);
        ds += __shfl_xor_sync(0xffffffffu, ds, off);
    }
    if (lane == 0) {
        out[b] = tanhf(dm);
        float sig = 1.f / (1.f + expf(-(ds + 2.f)));
        out[B + b] = (MAX_STD - MIN_STD) * sig + MIN_STD;
    }
}

extern "C" void kernel_launch(void* const* d_in, const int* in_sizes, int n_in,
                              void* d_out, int out_size) {
    const float* state  = (const float*)d_in[0];
    const float* w_fc1  = (const float*)d_in[1];
    const float* w_rec1 = (const float*)d_in[2];
    const float* w_fc2  = (const float*)d_in[3];
    const float* w_rec2 = (const float*)d_in[4];
    const float* w_mean = (const float*)d_in[5];
    const float* w_std  = (const float*)d_in[6];
    const float* a1 = (const float*)d_in[7];
    const float* b1 = (const float*)d_in[8];
    const float* t1 = (const float*)d_in[9];
    const float* a2 = (const float*)d_in[10];
    const float* b2 = (const float*)d_in[11];
    const float* t2 = (const float*)d_in[12];
    float* out = (float*)d_out;

    int B = in_sizes[0] / STATE_DIM;

    snn_transpose_kernel<<<(HIDDEN * HIDDEN + 255) / 256, 256>>>(w_fc1, w_rec1, w_fc2, w_rec2);

    int total_threads = B * 32;                    // one warp per element
    int blocks = (total_threads + 127) / 128;
    snn_main_kernel<<<blocks, 128>>>(state, w_mean, w_std,
                                     a1, b1, t1, a2, b2, t2, out, B);
}